// round 3
// baseline (speedup 1.0000x reference)
#include <cuda_runtime.h>
#include <math.h>

#define TBL_N   2048
#define TBL_NF  2048.0f

// (value, secant-slope) per cell of the fused function f(x) = wb*silu(x) + ws*spline(x)
__device__ float2 g_tab[TBL_N];

// ---------------------------------------------------------------------------
// Exact reference function (uniform-knot cubic B-spline, scipy-style clamp).
// Used only in the tiny prologue to populate the LUT.
// ---------------------------------------------------------------------------
__device__ __forceinline__ float ref_f(float x, const float* __restrict__ coef,
                                       float wb, float ws) {
    float fi = x * 13.0f;
    int i = (int)fi;                 // x >= 0 here
    i = min(max(i, 3), 9);           // clip -> polynomial extrapolation
    float u = fi - (float)i;
    float c0 = __ldg(coef + i - 3);
    float c1 = __ldg(coef + i - 2);
    float c2 = __ldg(coef + i - 1);
    float c3 = __ldg(coef + i);
    const float s = 1.0f / 6.0f;
    float a = (-c0 + 3.0f * c1 - 3.0f * c2 + c3) * s;
    float b = ( 3.0f * c0 - 6.0f * c1 + 3.0f * c2) * s;
    float c = (-3.0f * c0 + 3.0f * c2) * s;
    float d = ( c0 + 4.0f * c1 + c2) * s;
    float spline = fmaf(fmaf(fmaf(a, u, b), u, c), u, d);
    float sig = 1.0f / (1.0f + expf(-x));
    return fmaf(wb, x * sig, ws * spline);
}

// Prologue: 2048 cells; each thread computes both endpoints (no sync needed).
__global__ void build_tab_kernel(const float* __restrict__ coef,
                                 const float* __restrict__ wbp,
                                 const float* __restrict__ wsp) {
    int j = blockIdx.x * blockDim.x + threadIdx.x;
    if (j < TBL_N) {
        float wb = __ldg(wbp);
        float ws = __ldg(wsp);
        float x0 = (float)j       * (1.0f / TBL_NF);
        float x1 = (float)(j + 1) * (1.0f / TBL_NF);
        float v0 = ref_f(x0, coef, wb, ws);
        float v1 = ref_f(x1, coef, wb, ws);
        g_tab[j] = make_float2(v0, v1 - v0);
    }
}

// ---------------------------------------------------------------------------
// Main kernel: pure LUT + linear interp. ~8 SASS instructions per element.
// ---------------------------------------------------------------------------
__device__ __forceinline__ float lut1(float x, const float2* __restrict__ sTab) {
    float t = x * TBL_NF;
    int j = (int)t;                  // x >= 0: truncation == floor
    j = min(j, TBL_N - 1);           // defensive for x >= 1
    float u = t - (float)j;
    float2 vs = sTab[j];
    return fmaf(u, vs.y, vs.x);
}

#define V_PER_THREAD 4               // float4s per thread per loop iteration

__global__ void __launch_bounds__(256)
residual_act_lut_kernel(const float4* __restrict__ x4,
                        float4* __restrict__ out4,
                        int n4) {
    __shared__ float2 sTab[TBL_N];
    {   // fill 16 KB table: 1024 float4 / 256 threads = 4 vec loads each
        const float4* src = (const float4*)g_tab;
        float4* dst = (float4*)sTab;
        #pragma unroll
        for (int i = 0; i < 4; i++)
            dst[threadIdx.x + i * 256] = src[threadIdx.x + i * 256];
    }
    __syncthreads();

    const int tile = 256 * V_PER_THREAD;                 // float4s per block-iter
    for (int base0 = blockIdx.x * tile; base0 < n4; base0 += gridDim.x * tile) {
        int base = base0 + threadIdx.x;
        if (base0 + tile <= n4) {
            float4 xv[V_PER_THREAD];
            #pragma unroll
            for (int k = 0; k < V_PER_THREAD; k++)
                xv[k] = x4[base + k * 256];
            #pragma unroll
            for (int k = 0; k < V_PER_THREAD; k++) {
                float4 ov;
                ov.x = lut1(xv[k].x, sTab);
                ov.y = lut1(xv[k].y, sTab);
                ov.z = lut1(xv[k].z, sTab);
                ov.w = lut1(xv[k].w, sTab);
                out4[base + k * 256] = ov;
            }
        } else {
            #pragma unroll
            for (int k = 0; k < V_PER_THREAD; k++) {
                int idx = base + k * 256;
                if (idx < n4) {
                    float4 xv = x4[idx];
                    float4 ov;
                    ov.x = lut1(xv.x, sTab);
                    ov.y = lut1(xv.y, sTab);
                    ov.z = lut1(xv.z, sTab);
                    ov.w = lut1(xv.w, sTab);
                    out4[idx] = ov;
                }
            }
        }
    }
}

// Scalar tail for n % 4 != 0 (defensive; n = 2^24 in practice). Reads g_tab directly.
__global__ void residual_act_tail_kernel(const float* __restrict__ x,
                                         float* __restrict__ out,
                                         int start, int n) {
    int idx = start + blockIdx.x * blockDim.x + threadIdx.x;
    if (idx < n) {
        float xv = x[idx];
        float t = xv * TBL_NF;
        int j = min((int)t, TBL_N - 1);
        float u = t - (float)j;
        float2 vs = g_tab[j];
        out[idx] = fmaf(u, vs.y, vs.x);
    }
}

extern "C" void kernel_launch(void* const* d_in, const int* in_sizes, int n_in,
                              void* d_out, int out_size) {
    const float* x    = (const float*)d_in[0];   // [N] activations
    const float* coef = (const float*)d_in[1];   // [10] spline coefficients
    const float* wb   = (const float*)d_in[2];   // [1] w_basis
    const float* ws   = (const float*)d_in[3];   // [1] w_spline
    float* out        = (float*)d_out;

    int n  = in_sizes[0];
    int n4 = n / 4;

    build_tab_kernel<<<TBL_N / 256, 256>>>(coef, wb, ws);

    if (n4 > 0) {
        const int tile = 256 * V_PER_THREAD;
        int work_blocks = (n4 + tile - 1) / tile;
        int blocks = work_blocks < 1184 ? work_blocks : 1184;  // ~8 blocks/SM persistent
        residual_act_lut_kernel<<<blocks, 256>>>(
            (const float4*)x, (float4*)out, n4);
    }
    int tail = n - n4 * 4;
    if (tail > 0) {
        residual_act_tail_kernel<<<1, 256>>>(x, out, n4 * 4, n);
    }
}

// round 4
// speedup vs baseline: 1.0084x; 1.0084x over previous
#include <cuda_runtime.h>
#include <math.h>

// Combined per-interval cubic: f(x) ≈ ((P.x*u + P.y)*u + P.z)*u + P.w,
// u = 13x - i, interval i = clamp(floor(13x), 3, 9), index iv = i-3 in [0,6].
// P folds BOTH ws*spline (exact) and wb*silu (Chebyshev cubic fit, err ~6e-6).
__device__ float4 g_poly[7];

// ---------------------------------------------------------------------------
// Prologue (7 threads, fp64): exact spline segment poly + cubic fit of silu.
// ---------------------------------------------------------------------------
__global__ void build_poly_kernel(const float* __restrict__ coef,
                                  const float* __restrict__ wbp,
                                  const float* __restrict__ wsp) {
    int iv = threadIdx.x;            // 0..6 -> knot interval i = iv+3
    if (iv >= 7) return;
    double wb = (double)__ldg(wbp);
    double ws = (double)__ldg(wsp);
    int i = iv + 3;

    // --- exact uniform cubic B-spline segment, monomial in u ---
    double c0 = (double)__ldg(coef + iv + 0);
    double c1 = (double)__ldg(coef + iv + 1);
    double c2 = (double)__ldg(coef + iv + 2);
    double c3 = (double)__ldg(coef + iv + 3);
    const double s = 1.0 / 6.0;
    double sa = (-c0 + 3.0 * c1 - 3.0 * c2 + c3) * s;   // u^3
    double sb = ( 3.0 * c0 - 6.0 * c1 + 3.0 * c2) * s;  // u^2
    double sc = (-3.0 * c0 + 3.0 * c2) * s;             // u^1
    double sd = ( c0 + 4.0 * c1 + c2) * s;              // u^0

    // --- cubic Chebyshev-node fit of silu(x), x = (u+i)/13, over the u-range
    //     this interval actually serves (boundary intervals extrapolate) ---
    double ulo = (iv == 0) ? -3.0 : 0.0;
    double uhi = (iv == 6) ?  4.0 : 1.0;
    double mid = 0.5 * (ulo + uhi), rad = 0.5 * (uhi - ulo);
    double un[4], fv[4];
    for (int k = 0; k < 4; k++) {
        un[k] = mid + rad * cos((2.0 * k + 1.0) * 0.39269908169872414); // (2k+1)pi/8
        double xx = (un[k] + (double)i) / 13.0;
        fv[k] = xx / (1.0 + exp(-xx));                  // silu
    }
    // Newton divided differences
    double d0 = fv[0];
    double d01 = (fv[1] - fv[0]) / (un[1] - un[0]);
    double d12 = (fv[2] - fv[1]) / (un[2] - un[1]);
    double d23 = (fv[3] - fv[2]) / (un[3] - un[2]);
    double d012 = (d12 - d01) / (un[2] - un[0]);
    double d123 = (d23 - d12) / (un[3] - un[1]);
    double d0123 = (d123 - d012) / (un[3] - un[0]);
    // Newton -> monomial
    double e0 = un[0] + un[1], e01 = un[0] * un[1];
    double A3 = d0123;
    double A2 = d012 - d0123 * (un[0] + un[1] + un[2]);
    double A1 = d01 - d012 * e0 + d0123 * (e01 + un[0] * un[2] + un[1] * un[2]);
    double A0 = d0 - d01 * un[0] + d012 * e01 - d0123 * e01 * un[2];

    float4 p;
    p.x = (float)(ws * sa + wb * A3);
    p.y = (float)(ws * sb + wb * A2);
    p.z = (float)(ws * sc + wb * A1);
    p.w = (float)(ws * sd + wb * A0);
    g_poly[iv] = p;
}

// ---------------------------------------------------------------------------
// Main kernel: ~11 issue slots per element, conflict-free LDS.128 table.
// ---------------------------------------------------------------------------
__device__ __forceinline__ float eval_one(float x, const float4* __restrict__ sPoly) {
    float fi = x * 13.0f;
    int j = (int)fi;                 // x >= 0: truncation == floor
    j = min(max(j, 3), 9);           // scipy clip -> polynomial extrapolation
    float u = fi - (float)j;
    float4 p = sPoly[j - 3];         // 7 entries x 16B: disjoint banks, broadcast-dedup
    return fmaf(fmaf(fmaf(p.x, u, p.y), u, p.z), u, p.w);
}

#define V_PER_THREAD 4               // float4s per thread per loop iteration

__global__ void __launch_bounds__(256)
residual_act_kernel(const float4* __restrict__ x4,
                    float4* __restrict__ out4,
                    int n4) {
    __shared__ float4 sPoly[7];
    if (threadIdx.x < 7) sPoly[threadIdx.x] = g_poly[threadIdx.x];
    __syncthreads();

    const int tile = 256 * V_PER_THREAD;
    for (int base0 = blockIdx.x * tile; base0 < n4; base0 += gridDim.x * tile) {
        int base = base0 + threadIdx.x;
        if (base0 + tile <= n4) {
            float4 xv[V_PER_THREAD];
            #pragma unroll
            for (int k = 0; k < V_PER_THREAD; k++)
                xv[k] = x4[base + k * 256];
            #pragma unroll
            for (int k = 0; k < V_PER_THREAD; k++) {
                float4 ov;
                ov.x = eval_one(xv[k].x, sPoly);
                ov.y = eval_one(xv[k].y, sPoly);
                ov.z = eval_one(xv[k].z, sPoly);
                ov.w = eval_one(xv[k].w, sPoly);
                out4[base + k * 256] = ov;
            }
        } else {
            #pragma unroll
            for (int k = 0; k < V_PER_THREAD; k++) {
                int idx = base + k * 256;
                if (idx < n4) {
                    float4 xv = x4[idx];
                    float4 ov;
                    ov.x = eval_one(xv.x, sPoly);
                    ov.y = eval_one(xv.y, sPoly);
                    ov.z = eval_one(xv.z, sPoly);
                    ov.w = eval_one(xv.w, sPoly);
                    out4[idx] = ov;
                }
            }
        }
    }
}

// Scalar tail (n % 4 != 0 — defensive; n = 2^24 in practice).
__global__ void residual_act_tail_kernel(const float* __restrict__ x,
                                         float* __restrict__ out,
                                         int start, int n) {
    int idx = start + blockIdx.x * blockDim.x + threadIdx.x;
    if (idx < n) {
        float fi = x[idx] * 13.0f;
        int j = min(max((int)fi, 3), 9);
        float u = fi - (float)j;
        float4 p = g_poly[j - 3];
        out[idx] = fmaf(fmaf(fmaf(p.x, u, p.y), u, p.z), u, p.w);
    }
}

extern "C" void kernel_launch(void* const* d_in, const int* in_sizes, int n_in,
                              void* d_out, int out_size) {
    const float* x    = (const float*)d_in[0];   // [N] activations
    const float* coef = (const float*)d_in[1];   // [10] spline coefficients
    const float* wb   = (const float*)d_in[2];   // [1] w_basis
    const float* ws   = (const float*)d_in[3];   // [1] w_spline
    float* out        = (float*)d_out;

    int n  = in_sizes[0];
    int n4 = n / 4;

    build_poly_kernel<<<1, 32>>>(coef, wb, ws);

    if (n4 > 0) {
        const int tile = 256 * V_PER_THREAD;
        int work_blocks = (n4 + tile - 1) / tile;
        int blocks = work_blocks < 1184 ? work_blocks : 1184;  // ~8 blocks/SM persistent
        residual_act_kernel<<<blocks, 256>>>((const float4*)x, (float4*)out, n4);
    }
    int tail = n - n4 * 4;
    if (tail > 0) {
        residual_act_tail_kernel<<<1, 256>>>(x, out, n4 * 4, n);
    }
}

// round 5
// speedup vs baseline: 1.0096x; 1.0012x over previous
#include <cuda_runtime.h>
#include <math.h>

// Combined per-interval cubic: f(x) ≈ ((P.x*u+P.y)*u+P.z)*u+P.w,
// u = 13x - i, i = clamp(floor(13x), 3, 9). P folds ws*spline (exact) and
// wb*silu (cubic Chebyshev fit per interval, err ~6e-6).
__device__ float4 g_poly[7];   // used only by the defensive scalar tail

// ---------------------------------------------------------------------------
// In-kernel table build (threads 0..6). fp64 HW arithmetic + one fast __expf.
// ---------------------------------------------------------------------------
__device__ __forceinline__ void build_poly_smem(float4* sPoly,
                                                const float* __restrict__ coef,
                                                const float* __restrict__ wbp,
                                                const float* __restrict__ wsp) {
    int iv = threadIdx.x;            // 0..6 -> knot interval i = iv+3
    if (iv < 7) {
        double wb = (double)__ldg(wbp);
        double ws = (double)__ldg(wsp);
        int i = iv + 3;

        // exact uniform cubic B-spline segment, monomial in u
        double c0 = (double)__ldg(coef + iv + 0);
        double c1 = (double)__ldg(coef + iv + 1);
        double c2 = (double)__ldg(coef + iv + 2);
        double c3 = (double)__ldg(coef + iv + 3);
        const double s = 1.0 / 6.0;
        double sa = (-c0 + 3.0 * c1 - 3.0 * c2 + c3) * s;
        double sb = ( 3.0 * c0 - 6.0 * c1 + 3.0 * c2) * s;
        double sc = (-3.0 * c0 + 3.0 * c2) * s;
        double sd = ( c0 + 4.0 * c1 + c2) * s;

        // cubic Chebyshev fit of silu over this interval's served u-range
        double ulo = (iv == 0) ? -3.0 : 0.0;
        double uhi = (iv == 6) ?  4.0 : 1.0;
        double mid = 0.5 * (ulo + uhi), rad = 0.5 * (uhi - ulo);
        const double cn[4] = { 0.9238795325112867,  0.3826834323650898,
                              -0.3826834323650898, -0.9238795325112867 };
        double un[4], fv[4];
        #pragma unroll
        for (int k = 0; k < 4; k++) {
            un[k] = mid + rad * cn[k];
            double xx = (un[k] + (double)i) * (1.0 / 13.0);
            float  ex = __expf((float)(-xx));          // only transcendental
            fv[k] = xx / (1.0 + (double)ex);           // silu(xx)
        }
        double d0   = fv[0];
        double d01  = (fv[1] - fv[0]) / (un[1] - un[0]);
        double d12  = (fv[2] - fv[1]) / (un[2] - un[1]);
        double d23  = (fv[3] - fv[2]) / (un[3] - un[2]);
        double d012 = (d12 - d01) / (un[2] - un[0]);
        double d123 = (d23 - d12) / (un[3] - un[1]);
        double d0123 = (d123 - d012) / (un[3] - un[0]);
        double e0 = un[0] + un[1], e01 = un[0] * un[1];
        double A3 = d0123;
        double A2 = d012 - d0123 * (un[0] + un[1] + un[2]);
        double A1 = d01 - d012 * e0 + d0123 * (e01 + un[0] * un[2] + un[1] * un[2]);
        double A0 = d0 - d01 * un[0] + d012 * e01 - d0123 * e01 * un[2];

        float4 p;
        p.x = (float)(ws * sa + wb * A3);
        p.y = (float)(ws * sb + wb * A2);
        p.z = (float)(ws * sc + wb * A1);
        p.w = (float)(ws * sd + wb * A0);
        sPoly[iv] = p;
        g_poly[iv] = p;              // for the (unused-in-practice) tail kernel
    }
}

__device__ __forceinline__ float eval_one(float x, const float4* __restrict__ sPoly) {
    float fi = x * 13.0f;
    int j = (int)fi;                 // x >= 0: truncation == floor
    j = min(max(j, 3), 9);
    float u = fi - (float)j;
    float4 p = sPoly[j - 3];         // 7x16B: distinct banks + broadcast dedup
    return fmaf(fmaf(fmaf(p.x, u, p.y), u, p.z), u, p.w);
}

#define V_PER_THREAD 4

__global__ void __launch_bounds__(256)
residual_act_fused_kernel(const float4* __restrict__ x4,
                          float4* __restrict__ out4,
                          int n4,
                          const float* __restrict__ coef,
                          const float* __restrict__ wbp,
                          const float* __restrict__ wsp) {
    __shared__ float4 sPoly[7];
    build_poly_smem(sPoly, coef, wbp, wsp);
    __syncthreads();

    const int tile   = 256 * V_PER_THREAD;        // float4s per block-iter
    const int stride = gridDim.x * tile;

    int b0 = blockIdx.x * tile;                   // tile base (block-level)
    int b  = b0 + threadIdx.x;

    // --- software pipeline: prefetch next tile while computing current ---
    float4 cur[V_PER_THREAD];
    bool curFull = (b0 + tile <= n4);
    if (curFull) {
        #pragma unroll
        for (int k = 0; k < V_PER_THREAD; k++) cur[k] = x4[b + k * 256];
    }

    while (b0 < n4) {
        int nb0 = b0 + stride;
        int nb  = b + stride;
        float4 nxt[V_PER_THREAD];
        bool nxtFull = (nb0 < n4) && (nb0 + tile <= n4);
        if (nxtFull) {
            #pragma unroll
            for (int k = 0; k < V_PER_THREAD; k++) nxt[k] = x4[nb + k * 256];
        }

        if (curFull) {
            #pragma unroll
            for (int k = 0; k < V_PER_THREAD; k++) {
                float4 ov;
                ov.x = eval_one(cur[k].x, sPoly);
                ov.y = eval_one(cur[k].y, sPoly);
                ov.z = eval_one(cur[k].z, sPoly);
                ov.w = eval_one(cur[k].w, sPoly);
                out4[b + k * 256] = ov;
            }
        } else {
            #pragma unroll
            for (int k = 0; k < V_PER_THREAD; k++) {
                int idx = b + k * 256;
                if (idx < n4) {
                    float4 xv = x4[idx];
                    float4 ov;
                    ov.x = eval_one(xv.x, sPoly);
                    ov.y = eval_one(xv.y, sPoly);
                    ov.z = eval_one(xv.z, sPoly);
                    ov.w = eval_one(xv.w, sPoly);
                    out4[idx] = ov;
                }
            }
        }

        b0 = nb0; b = nb; curFull = nxtFull;
        #pragma unroll
        for (int k = 0; k < V_PER_THREAD; k++) cur[k] = nxt[k];
    }
}

// Scalar tail (n % 4 != 0 — defensive; n = 2^24 in practice).
__global__ void residual_act_tail_kernel(const float* __restrict__ x,
                                         float* __restrict__ out,
                                         int start, int n) {
    int idx = start + blockIdx.x * blockDim.x + threadIdx.x;
    if (idx < n) {
        float fi = x[idx] * 13.0f;
        int j = min(max((int)fi, 3), 9);
        float u = fi - (float)j;
        float4 p = g_poly[j - 3];
        out[idx] = fmaf(fmaf(fmaf(p.x, u, p.y), u, p.z), u, p.w);
    }
}

extern "C" void kernel_launch(void* const* d_in, const int* in_sizes, int n_in,
                              void* d_out, int out_size) {
    const float* x    = (const float*)d_in[0];   // [N] activations
    const float* coef = (const float*)d_in[1];   // [10] spline coefficients
    const float* wb   = (const float*)d_in[2];   // [1] w_basis
    const float* ws   = (const float*)d_in[3];   // [1] w_spline
    float* out        = (float*)d_out;

    int n  = in_sizes[0];
    int n4 = n / 4;

    if (n4 > 0) {
        const int tile = 256 * V_PER_THREAD;
        int work_blocks = (n4 + tile - 1) / tile;
        int blocks = work_blocks < 1184 ? work_blocks : 1184;  // persistent
        residual_act_fused_kernel<<<blocks, 256>>>(
            (const float4*)x, (float4*)out, n4, coef, wb, ws);
    }
    int tail = n - n4 * 4;
    if (tail > 0) {
        residual_act_tail_kernel<<<1, 256>>>(x, out, n4 * 4, n);
    }
}

// round 6
// speedup vs baseline: 1.0853x; 1.0749x over previous
#include <cuda_runtime.h>
#include <math.h>

// Combined per-interval cubic: f(x) ≈ ((P.x*u+P.y)*u+P.z)*u+P.w,
// u = 13x - i, i = clamp(floor(13x), 3, 9). P folds ws*spline (exact) and
// wb*silu (per-interval cubic Chebyshev fit, err ~6e-6).
__device__ float4 g_poly[7];   // only for the defensive scalar-tail kernel

// ---------------------------------------------------------------------------
// In-kernel table build, PURE fp32 (threads 0..6; ~60 instrs; no fp64).
// ---------------------------------------------------------------------------
__device__ __forceinline__ void build_poly_smem(float4* sPoly,
                                                const float* __restrict__ coef,
                                                const float* __restrict__ wbp,
                                                const float* __restrict__ wsp,
                                                bool writeGlobal) {
    int iv = threadIdx.x;            // 0..6 -> knot interval i = iv+3
    if (iv < 7) {
        float wb = __ldg(wbp);
        float ws = __ldg(wsp);
        int i = iv + 3;

        // exact uniform cubic B-spline segment, monomial in u
        float c0 = __ldg(coef + iv + 0);
        float c1 = __ldg(coef + iv + 1);
        float c2 = __ldg(coef + iv + 2);
        float c3 = __ldg(coef + iv + 3);
        const float s = 1.0f / 6.0f;
        float sa = (-c0 + 3.0f * c1 - 3.0f * c2 + c3) * s;
        float sb = ( 3.0f * c0 - 6.0f * c1 + 3.0f * c2) * s;
        float sc = (-3.0f * c0 + 3.0f * c2) * s;
        float sd = ( c0 + 4.0f * c1 + c2) * s;

        // cubic Chebyshev fit of silu over this interval's served u-range
        float ulo = (iv == 0) ? -3.0f : 0.0f;
        float uhi = (iv == 6) ?  4.0f : 1.0f;
        float mid = 0.5f * (ulo + uhi), rad = 0.5f * (uhi - ulo);
        const float cn0 =  0.92387953f, cn1 = 0.38268343f;
        float un[4], fv[4];
        un[0] = mid + rad * cn0;
        un[1] = mid + rad * cn1;
        un[2] = mid - rad * cn1;
        un[3] = mid - rad * cn0;
        #pragma unroll
        for (int k = 0; k < 4; k++) {
            float xx = (un[k] + (float)i) * (1.0f / 13.0f);
            fv[k] = xx / (1.0f + __expf(-xx));          // silu(xx)
        }
        float d0    = fv[0];
        float d01   = (fv[1] - fv[0]) / (un[1] - un[0]);
        float d12   = (fv[2] - fv[1]) / (un[2] - un[1]);
        float d23   = (fv[3] - fv[2]) / (un[3] - un[2]);
        float d012  = (d12 - d01) / (un[2] - un[0]);
        float d123  = (d23 - d12) / (un[3] - un[1]);
        float d0123 = (d123 - d012) / (un[3] - un[0]);
        float e0 = un[0] + un[1], e01 = un[0] * un[1];
        float A3 = d0123;
        float A2 = d012 - d0123 * (un[0] + un[1] + un[2]);
        float A1 = d01 - d012 * e0 + d0123 * (e01 + un[0] * un[2] + un[1] * un[2]);
        float A0 = d0 - d01 * un[0] + d012 * e01 - d0123 * e01 * un[2];

        float4 p;
        p.x = fmaf(ws, sa, wb * A3);
        p.y = fmaf(ws, sb, wb * A2);
        p.z = fmaf(ws, sc, wb * A1);
        p.w = fmaf(ws, sd, wb * A0);
        sPoly[iv] = p;
        if (writeGlobal) g_poly[iv] = p;
    }
}

__device__ __forceinline__ float eval_one(float x, const float4* __restrict__ sPoly) {
    float fi = x * 13.0f;
    int j = (int)fi;                 // x >= 0: truncation == floor
    j = min(max(j, 3), 9);           // scipy clip -> polynomial extrapolation
    float u = fi - (float)j;
    float4 p = sPoly[j - 3];         // 7x16B: distinct banks + broadcast dedup
    return fmaf(fmaf(fmaf(p.x, u, p.y), u, p.z), u, p.w);
}

#define V_PER_THREAD 4

__global__ void __launch_bounds__(256)
residual_act_fused_kernel(const float4* __restrict__ x4,
                          float4* __restrict__ out4,
                          int n4, int hasTail,
                          const float* __restrict__ coef,
                          const float* __restrict__ wbp,
                          const float* __restrict__ wsp) {
    __shared__ float4 sPoly[7];
    build_poly_smem(sPoly, coef, wbp, wsp, hasTail && blockIdx.x == 0);
    __syncthreads();

    const int tile = 256 * V_PER_THREAD;          // float4s per block-iter
    for (int base0 = blockIdx.x * tile; base0 < n4; base0 += gridDim.x * tile) {
        int base = base0 + threadIdx.x;
        if (base0 + tile <= n4) {
            float4 xv[V_PER_THREAD];
            #pragma unroll
            for (int k = 0; k < V_PER_THREAD; k++)
                xv[k] = x4[base + k * 256];
            #pragma unroll
            for (int k = 0; k < V_PER_THREAD; k++) {
                float4 ov;
                ov.x = eval_one(xv[k].x, sPoly);
                ov.y = eval_one(xv[k].y, sPoly);
                ov.z = eval_one(xv[k].z, sPoly);
                ov.w = eval_one(xv[k].w, sPoly);
                out4[base + k * 256] = ov;
            }
        } else {
            #pragma unroll
            for (int k = 0; k < V_PER_THREAD; k++) {
                int idx = base + k * 256;
                if (idx < n4) {
                    float4 xv = x4[idx];
                    float4 ov;
                    ov.x = eval_one(xv.x, sPoly);
                    ov.y = eval_one(xv.y, sPoly);
                    ov.z = eval_one(xv.z, sPoly);
                    ov.w = eval_one(xv.w, sPoly);
                    out4[idx] = ov;
                }
            }
        }
    }
}

// Scalar tail (n % 4 != 0 — defensive; n = 2^24 in practice so never launched).
__global__ void residual_act_tail_kernel(const float* __restrict__ x,
                                         float* __restrict__ out,
                                         int start, int n) {
    int idx = start + blockIdx.x * blockDim.x + threadIdx.x;
    if (idx < n) {
        float fi = x[idx] * 13.0f;
        int j = min(max((int)fi, 3), 9);
        float u = fi - (float)j;
        float4 p = g_poly[j - 3];
        out[idx] = fmaf(fmaf(fmaf(p.x, u, p.y), u, p.z), u, p.w);
    }
}

extern "C" void kernel_launch(void* const* d_in, const int* in_sizes, int n_in,
                              void* d_out, int out_size) {
    const float* x    = (const float*)d_in[0];   // [N] activations
    const float* coef = (const float*)d_in[1];   // [10] spline coefficients
    const float* wb   = (const float*)d_in[2];   // [1] w_basis
    const float* ws   = (const float*)d_in[3];   // [1] w_spline
    float* out        = (float*)d_out;

    int n    = in_sizes[0];
    int n4   = n / 4;
    int tail = n - n4 * 4;

    if (n4 > 0) {
        const int tile = 256 * V_PER_THREAD;
        int work_blocks = (n4 + tile - 1) / tile;
        int blocks = work_blocks < 1184 ? work_blocks : 1184;  // persistent
        residual_act_fused_kernel<<<blocks, 256>>>(
            (const float4*)x, (float4*)out, n4, tail > 0 ? 1 : 0, coef, wb, ws);
    }
    if (tail > 0) {
        residual_act_tail_kernel<<<1, 256>>>(x, out, n4 * 4, n);
    }
}

// round 7
// speedup vs baseline: 1.1898x; 1.0963x over previous
#include <cuda_runtime.h>
#include <math.h>

// Combined per-interval cubic: f(x) ≈ ((P.x*u+P.y)*u+P.z)*u+P.w,
// u = 13x - i, i = clamp(floor(13x), 3, 9). P folds ws*spline (exact) and
// wb*silu (per-interval cubic Chebyshev fit, err ~6e-6).
__device__ float4 g_poly[7];   // only for the defensive scalar-tail kernel

// ---------------------------------------------------------------------------
// In-kernel table build, pure fp32 (threads 0..6; ~60 instrs).
// ---------------------------------------------------------------------------
__device__ __forceinline__ void build_poly_smem(float4* sPoly,
                                                const float* __restrict__ coef,
                                                const float* __restrict__ wbp,
                                                const float* __restrict__ wsp,
                                                bool writeGlobal) {
    int iv = threadIdx.x;            // 0..6 -> knot interval i = iv+3
    if (iv < 7) {
        float wb = __ldg(wbp);
        float ws = __ldg(wsp);
        int i = iv + 3;

        // exact uniform cubic B-spline segment, monomial in u
        float c0 = __ldg(coef + iv + 0);
        float c1 = __ldg(coef + iv + 1);
        float c2 = __ldg(coef + iv + 2);
        float c3 = __ldg(coef + iv + 3);
        const float s = 1.0f / 6.0f;
        float sa = (-c0 + 3.0f * c1 - 3.0f * c2 + c3) * s;
        float sb = ( 3.0f * c0 - 6.0f * c1 + 3.0f * c2) * s;
        float sc = (-3.0f * c0 + 3.0f * c2) * s;
        float sd = ( c0 + 4.0f * c1 + c2) * s;

        // cubic Chebyshev fit of silu over this interval's served u-range
        float ulo = (iv == 0) ? -3.0f : 0.0f;
        float uhi = (iv == 6) ?  4.0f : 1.0f;
        float mid = 0.5f * (ulo + uhi), rad = 0.5f * (uhi - ulo);
        const float cn0 =  0.92387953f, cn1 = 0.38268343f;
        float un[4], fv[4];
        un[0] = mid + rad * cn0;
        un[1] = mid + rad * cn1;
        un[2] = mid - rad * cn1;
        un[3] = mid - rad * cn0;
        #pragma unroll
        for (int k = 0; k < 4; k++) {
            float xx = (un[k] + (float)i) * (1.0f / 13.0f);
            fv[k] = xx / (1.0f + __expf(-xx));          // silu(xx)
        }
        float d0    = fv[0];
        float d01   = (fv[1] - fv[0]) / (un[1] - un[0]);
        float d12   = (fv[2] - fv[1]) / (un[2] - un[1]);
        float d23   = (fv[3] - fv[2]) / (un[3] - un[2]);
        float d012  = (d12 - d01) / (un[2] - un[0]);
        float d123  = (d23 - d12) / (un[3] - un[1]);
        float d0123 = (d123 - d012) / (un[3] - un[0]);
        float e0 = un[0] + un[1], e01 = un[0] * un[1];
        float A3 = d0123;
        float A2 = d012 - d0123 * (un[0] + un[1] + un[2]);
        float A1 = d01 - d012 * e0 + d0123 * (e01 + un[0] * un[2] + un[1] * un[2]);
        float A0 = d0 - d01 * un[0] + d012 * e01 - d0123 * e01 * un[2];

        float4 p;
        p.x = fmaf(ws, sa, wb * A3);
        p.y = fmaf(ws, sb, wb * A2);
        p.z = fmaf(ws, sc, wb * A1);
        p.w = fmaf(ws, sd, wb * A0);
        sPoly[iv] = p;
        if (writeGlobal) g_poly[iv] = p;
    }
}

__device__ __forceinline__ float eval_one(float x, const float4* __restrict__ sPoly) {
    float fi = x * 13.0f;
    int j = (int)fi;                 // x >= 0: truncation == floor
    j = min(max(j, 3), 9);           // scipy clip -> polynomial extrapolation
    float u = fi - (float)j;
    float4 p = sPoly[j - 3];         // 7x16B: distinct banks + broadcast dedup
    return fmaf(fmaf(fmaf(p.x, u, p.y), u, p.z), u, p.w);
}

#define V_PER_THREAD 4

__global__ void __launch_bounds__(256)
residual_act_fused_kernel(const float4* __restrict__ x4,
                          float4* __restrict__ out4,
                          int n4, int hasTail,
                          const float* __restrict__ coef,
                          const float* __restrict__ wbp,
                          const float* __restrict__ wsp) {
    __shared__ float4 sPoly[7];
    build_poly_smem(sPoly, coef, wbp, wsp, hasTail && blockIdx.x == 0);
    __syncthreads();

    const int tile = 256 * V_PER_THREAD;          // float4s per block-iter
    for (int base0 = blockIdx.x * tile; base0 < n4; base0 += gridDim.x * tile) {
        int base = base0 + threadIdx.x;
        if (base0 + tile <= n4) {
            float4 xv[V_PER_THREAD];
            #pragma unroll
            for (int k = 0; k < V_PER_THREAD; k++)
                xv[k] = x4[base + k * 256];
            #pragma unroll
            for (int k = 0; k < V_PER_THREAD; k++) {
                float4 ov;
                ov.x = eval_one(xv[k].x, sPoly);
                ov.y = eval_one(xv[k].y, sPoly);
                ov.z = eval_one(xv[k].z, sPoly);
                ov.w = eval_one(xv[k].w, sPoly);
                // streaming store: evict-first so output doesn't evict x from L2
                __stcs(out4 + base + k * 256, ov);
            }
        } else {
            #pragma unroll
            for (int k = 0; k < V_PER_THREAD; k++) {
                int idx = base + k * 256;
                if (idx < n4) {
                    float4 xv = x4[idx];
                    float4 ov;
                    ov.x = eval_one(xv.x, sPoly);
                    ov.y = eval_one(xv.y, sPoly);
                    ov.z = eval_one(xv.z, sPoly);
                    ov.w = eval_one(xv.w, sPoly);
                    __stcs(out4 + idx, ov);
                }
            }
        }
    }
}

// Scalar tail (n % 4 != 0 — defensive; n = 2^24 in practice so never launched).
__global__ void residual_act_tail_kernel(const float* __restrict__ x,
                                         float* __restrict__ out,
                                         int start, int n) {
    int idx = start + blockIdx.x * blockDim.x + threadIdx.x;
    if (idx < n) {
        float fi = x[idx] * 13.0f;
        int j = min(max((int)fi, 3), 9);
        float u = fi - (float)j;
        float4 p = g_poly[j - 3];
        out[idx] = fmaf(fmaf(fmaf(p.x, u, p.y), u, p.z), u, p.w);
    }
}

extern "C" void kernel_launch(void* const* d_in, const int* in_sizes, int n_in,
                              void* d_out, int out_size) {
    const float* x    = (const float*)d_in[0];   // [N] activations
    const float* coef = (const float*)d_in[1];   // [10] spline coefficients
    const float* wb   = (const float*)d_in[2];   // [1] w_basis
    const float* ws   = (const float*)d_in[3];   // [1] w_spline
    float* out        = (float*)d_out;

    int n    = in_sizes[0];
    int n4   = n / 4;
    int tail = n - n4 * 4;

    if (n4 > 0) {
        const int tile = 256 * V_PER_THREAD;
        int work_blocks = (n4 + tile - 1) / tile;
        int blocks = work_blocks < 1184 ? work_blocks : 1184;  // persistent
        residual_act_fused_kernel<<<blocks, 256>>>(
            (const float4*)x, (float4*)out, n4, tail > 0 ? 1 : 0, coef, wb, ws);
    }
    if (tail > 0) {
        residual_act_tail_kernel<<<1, 256>>>(x, out, n4 * 4, n);
    }
}